// round 16
// baseline (speedup 1.0000x reference)
#include <cuda_runtime.h>
#include <cstdint>

// Problem constants
constexpr int B_  = 4;
constexpr int L_  = 2048;
constexpr int D_  = 1024;
constexpr int H_  = 16;
constexpr int HD_ = 64;
constexpr int M_  = B_ * L_;          // 8192 rows
constexpr float SCALE2 = 0.125f * 1.4426950408889634f;  // 1/sqrt(64) * log2(e)

// Scratch (allocation-free rule: __device__ globals)
__device__ float g_Q[(size_t)M_ * D_];
__device__ float g_K[(size_t)M_ * D_];
__device__ float g_V[(size_t)M_ * D_];
__device__ float g_att[(size_t)M_ * D_];

// ---------------------------------------------------------------------------
// helpers
// ---------------------------------------------------------------------------
__device__ __forceinline__ float f2tf(float f) {
    unsigned u;
    asm("cvt.rna.tf32.f32 %0, %1;" : "=r"(u) : "f"(f));
    return __uint_as_float(u);
}

__device__ __forceinline__ float ex2f(float x) {
    float y;
    asm("ex2.approx.f32 %0, %1;" : "=f"(y) : "f"(x));
    return y;
}

// D = A(16x8 row) * B(8x8 col) + D, tf32 in, fp32 accum
__device__ __forceinline__ void mma8(float* c, const unsigned* a, const unsigned* b) {
    asm volatile(
        "mma.sync.aligned.m16n8k8.row.col.f32.tf32.tf32.f32 "
        "{%0,%1,%2,%3}, {%4,%5,%6,%7}, {%8,%9}, {%0,%1,%2,%3};"
        : "+f"(c[0]), "+f"(c[1]), "+f"(c[2]), "+f"(c[3])
        : "r"(a[0]), "r"(a[1]), "r"(a[2]), "r"(a[3]), "r"(b[0]), "r"(b[1]));
}

// ldmatrix x4: 16B "rows" = 4 tf32; one 32-bit word per thread per matrix
__device__ __forceinline__ void ldsm4(unsigned& r0, unsigned& r1, unsigned& r2,
                                      unsigned& r3, const float* p) {
    unsigned a = (unsigned)__cvta_generic_to_shared(p);
    asm volatile("ldmatrix.sync.aligned.m8n8.x4.shared.b16 {%0,%1,%2,%3}, [%4];"
                 : "=r"(r0), "=r"(r1), "=r"(r2), "=r"(r3) : "r"(a));
}

// ---------------------------------------------------------------------------
// tf32 GEMM (NT): C[M,1024] = A[M,1024]*W[1024,1024]^T + bias
// CTA tile 128(M) x 256(N), BK=16, 256 thr, 8 warps as 2(M)x4(N) ->
// 64x64 warp tiles (0.125 B/MAC LDS traffic). Double-buffered dynamic smem.
// ---------------------------------------------------------------------------
constexpr int KPAD = 20;
// dynamic smem word offsets
constexpr int GA0 = 0;                       // As buf0 [128][20]
constexpr int GA1 = GA0 + 128 * KPAD;        // As buf1
constexpr int GW0 = GA1 + 128 * KPAD;        // Ws buf0 [256][20]
constexpr int GW1 = GW0 + 256 * KPAD;        // Ws buf1
constexpr int GEMM_SMEM_BYTES = (GW1 + 256 * KPAD) * 4;   // 61440 B

__device__ __forceinline__ void gemm_body(
    const float* __restrict__ A, const float* __restrict__ W,
    const float* __restrict__ bias, float* __restrict__ C)
{
    extern __shared__ float sm[];
    const int t    = threadIdx.x;
    const int lane = t & 31;
    const int l7   = lane & 7;
    const int wid  = t >> 5;
    const int wm   = wid & 1;        // 2 warps in M (64 rows)
    const int wn   = wid >> 1;       // 4 warps in N (64 cols)
    const int rowB = blockIdx.y * 128;
    const int colB = blockIdx.x * 256;

    // staging map: A = 512 float4 (2/thread), W = 1024 float4 (4/thread)
    const int ra = t >> 1;                 // with k2 offset: rows t>>1 and +128? no:
    // A float4 idx = t + 256*k2 (k2<2): row = idx>>2 (0..127), col4 = idx&3
    // W float4 idx = t + 256*k2 (k2<4): row = idx>>2 (0..255), col4 = idx&3
    (void)ra;

    float acc[4][8][4] = {};

    float4 pa[2], pb[4];
    #pragma unroll
    for (int k2 = 0; k2 < 2; k2++) {
        const int i = t + 256 * k2, r = i >> 2, c4 = (i & 3) << 2;
        pa[k2] = *(const float4*)(A + (size_t)(rowB + r) * D_ + c4);
    }
    #pragma unroll
    for (int k2 = 0; k2 < 4; k2++) {
        const int i = t + 256 * k2, r = i >> 2, c4 = (i & 3) << 2;
        pb[k2] = *(const float4*)(W + (size_t)(colB + r) * D_ + c4);
    }

#define STASH(abuf, wbuf)                                                      \
    do {                                                                       \
        _Pragma("unroll")                                                      \
        for (int k2 = 0; k2 < 2; k2++) {                                       \
            const int i = t + 256 * k2, r = i >> 2, c4 = (i & 3) << 2;         \
            float4 v;                                                          \
            v.x = f2tf(pa[k2].x); v.y = f2tf(pa[k2].y);                        \
            v.z = f2tf(pa[k2].z); v.w = f2tf(pa[k2].w);                        \
            *(float4*)&sm[(abuf) + r * KPAD + c4] = v;                         \
        }                                                                      \
        _Pragma("unroll")                                                      \
        for (int k2 = 0; k2 < 4; k2++) {                                       \
            const int i = t + 256 * k2, r = i >> 2, c4 = (i & 3) << 2;         \
            float4 v;                                                          \
            v.x = f2tf(pb[k2].x); v.y = f2tf(pb[k2].y);                        \
            v.z = f2tf(pb[k2].z); v.w = f2tf(pb[k2].w);                        \
            *(float4*)&sm[(wbuf) + r * KPAD + c4] = v;                         \
        }                                                                      \
    } while (0)

    STASH(GA0, GW0);
    __syncthreads();

    for (int kt = 0; kt < 64; kt++) {
        const int cur  = kt & 1;
        const int aoff = cur ? GA1 : GA0;
        const int woff = cur ? GW1 : GW0;
        if (kt < 63) {
            const int ko = (kt + 1) * 16;
            #pragma unroll
            for (int k2 = 0; k2 < 2; k2++) {
                const int i = t + 256 * k2, r = i >> 2, c4 = (i & 3) << 2;
                pa[k2] = *(const float4*)(A + (size_t)(rowB + r) * D_ + ko + c4);
            }
            #pragma unroll
            for (int k2 = 0; k2 < 4; k2++) {
                const int i = t + 256 * k2, r = i >> 2, c4 = (i & 3) << 2;
                pb[k2] = *(const float4*)(W + (size_t)(colB + r) * D_ + ko + c4);
            }
        }
        #pragma unroll
        for (int kc = 0; kc < 2; kc++) {
            const int kk = kc * 8;
            const int m  = lane >> 3;
            unsigned af[4][4], bf[8][2];
            #pragma unroll
            for (int i = 0; i < 4; i++) {
                const int rr = wm * 64 + i * 16 + (m & 1) * 8 + l7;
                const int cc = kk + (m >> 1) * 4;
                ldsm4(af[i][0], af[i][1], af[i][2], af[i][3],
                      &sm[aoff + rr * KPAD + cc]);
            }
            #pragma unroll
            for (int jp = 0; jp < 4; jp++) {
                const int rr = wn * 64 + (jp * 2 + (m >> 1)) * 8 + l7;
                const int cc = kk + (m & 1) * 4;
                ldsm4(bf[jp*2][0], bf[jp*2][1], bf[jp*2+1][0], bf[jp*2+1][1],
                      &sm[woff + rr * KPAD + cc]);
            }
            #pragma unroll
            for (int i = 0; i < 4; i++)
                #pragma unroll
                for (int j = 0; j < 8; j++)
                    mma8(acc[i][j], af[i], bf[j]);
        }
        if (kt < 63) STASH(cur ? GA0 : GA1, cur ? GW0 : GW1);
        __syncthreads();
    }
#undef STASH

    const int gid = lane >> 2;
    const int tig = lane & 3;
    #pragma unroll
    for (int i = 0; i < 4; i++) {
        const int row = rowB + wm * 64 + i * 16 + gid;
        #pragma unroll
        for (int j = 0; j < 8; j++) {
            const int col = colB + wn * 64 + j * 8 + 2 * tig;
            const float bx = bias[col], by = bias[col + 1];
            float2 v0 = make_float2(acc[i][j][0] + bx, acc[i][j][1] + by);
            float2 v1 = make_float2(acc[i][j][2] + bx, acc[i][j][3] + by);
            *(float2*)&C[(size_t)row * D_ + col]       = v0;
            *(float2*)&C[(size_t)(row + 8) * D_ + col] = v1;
        }
    }
}

// Fused Q/K/V projection: grid.z selects which projection this block computes.
__global__ __launch_bounds__(256, 1) void gemm_qkv(
    const float* __restrict__ q,  const float* __restrict__ k,
    const float* __restrict__ v,
    const float* __restrict__ Wq, const float* __restrict__ bq,
    const float* __restrict__ Wk, const float* __restrict__ bk,
    const float* __restrict__ Wv, const float* __restrict__ bv)
{
    const float *A, *W, *bias;
    float* C;
    if (blockIdx.z == 0)      { A = q; W = Wq; bias = bq; C = g_Q; }
    else if (blockIdx.z == 1) { A = k; W = Wk; bias = bk; C = g_K; }
    else                      { A = v; W = Wv; bias = bv; C = g_V; }
    gemm_body(A, W, bias, C);
}

__global__ __launch_bounds__(256, 1) void gemm_o(
    const float* __restrict__ W, const float* __restrict__ bias,
    float* __restrict__ C)
{
    gemm_body(g_att, W, bias, C);
}

// ---------------------------------------------------------------------------
// Flash attention v2 (unchanged from best-passing R9 kernel), tf32 mma.sync.
// ---------------------------------------------------------------------------
constexpr int KS_W = 0;                 // Ks[64][64] swizzled
constexpr int VS_W = 4096;              // Vs[64][64] linear
constexpr int VT_W = 8192;              // Vt[64(hd)][64(key)] swizzled
constexpr int PS_W = 12288;             // Ps[64][64] swizzled
constexpr int ATT_SMEM_BYTES = 16384 * 4;   // 64 KB

__device__ __forceinline__ int swz(int row, int col) {
    return row * 64 + ((((col >> 2) ^ (row & 7)) << 2) | (col & 3));
}

__global__ __launch_bounds__(128, 3) void attn_tf32()
{
    extern __shared__ float sm[];
    float* Ks = sm + KS_W;
    float* Vs = sm + VS_W;
    float* Vt = sm + VT_W;
    float* Ps = sm + PS_W;

    const int t    = threadIdx.x;
    const int lane = t & 31;
    const int gid  = lane >> 2;
    const int tig  = lane & 3;
    const int l7   = lane & 7;
    const int wm   = t >> 5;
    const int b    = blockIdx.z;
    const int h    = blockIdx.y;
    const int qB   = blockIdx.x * 64;

    unsigned qa[8][4];
    {
        const float* Qg = g_Q + ((size_t)(b * L_ + qB + wm * 16)) * D_ + h * HD_;
        #pragma unroll
        for (int kc = 0; kc < 8; kc++) {
            const int k0 = kc * 8 + tig;
            qa[kc][0] = __float_as_uint(f2tf(Qg[(size_t)gid * D_ + k0]           * SCALE2));
            qa[kc][1] = __float_as_uint(f2tf(Qg[(size_t)(gid + 8) * D_ + k0]     * SCALE2));
            qa[kc][2] = __float_as_uint(f2tf(Qg[(size_t)gid * D_ + k0 + 4]       * SCALE2));
            qa[kc][3] = __float_as_uint(f2tf(Qg[(size_t)(gid + 8) * D_ + k0 + 4] * SCALE2));
        }
    }

    float o[8][4] = {};
    float m0 = -1e30f, m1 = -1e30f, l0 = 0.0f, l1 = 0.0f;
    const int rr  = wm * 16 + gid;
    const int thd = t & 63;
    const int tkg = (t >> 6) * 32;

    for (int kt = 0; kt < L_; kt += 64) {
        const float* Kg = g_K + ((size_t)(b * L_ + kt)) * D_ + h * HD_;
        const float* Vg = g_V + ((size_t)(b * L_ + kt)) * D_ + h * HD_;
        __syncthreads();
        for (int i = t; i < 64 * 16; i += 128) {
            const int r = i >> 4, c = (i & 15) * 4;
            float4 kv = *(const float4*)&Kg[(size_t)r * D_ + c];
            float4 vv = *(const float4*)&Vg[(size_t)r * D_ + c];
            float4 w;
            w.x = f2tf(kv.x); w.y = f2tf(kv.y); w.z = f2tf(kv.z); w.w = f2tf(kv.w);
            *(float4*)&Ks[swz(r, c)] = w;
            w.x = f2tf(vv.x); w.y = f2tf(vv.y); w.z = f2tf(vv.z); w.w = f2tf(vv.w);
            *(float4*)&Vs[r * 64 + c] = w;
        }
        __syncthreads();

        #pragma unroll
        for (int kk8 = 0; kk8 < 8; kk8++) {
            const int k0 = tkg + kk8 * 4;
            float4 w;
            w.x = Vs[(k0 + 0) * 64 + thd];
            w.y = Vs[(k0 + 1) * 64 + thd];
            w.z = Vs[(k0 + 2) * 64 + thd];
            w.w = Vs[(k0 + 3) * 64 + thd];
            *(float4*)&Vt[swz(thd, k0)] = w;
        }
        __syncthreads();

        float s[8][4] = {};
        #pragma unroll
        for (int kc = 0; kc < 8; kc++) {
            const int kk = kc * 8;
            unsigned bf[8][2];
            #pragma unroll
            for (int jp = 0; jp < 4; jp++) {
                const int m  = lane >> 3;
                const int kr = (jp * 2 + (m >> 1)) * 8 + l7;
                const int cc = kk + (m & 1) * 4;
                ldsm4(bf[jp*2][0], bf[jp*2][1], bf[jp*2+1][0], bf[jp*2+1][1],
                      &Ks[swz(kr, cc)]);
            }
            #pragma unroll
            for (int j = 0; j < 8; j++)
                mma8(s[j], qa[kc], bf[j]);
        }

        float mx0 = -1e30f, mx1 = -1e30f;
        #pragma unroll
        for (int j = 0; j < 8; j++) {
            mx0 = fmaxf(mx0, fmaxf(s[j][0], s[j][1]));
            mx1 = fmaxf(mx1, fmaxf(s[j][2], s[j][3]));
        }
        mx0 = fmaxf(mx0, __shfl_xor_sync(0xffffffffu, mx0, 1));
        mx0 = fmaxf(mx0, __shfl_xor_sync(0xffffffffu, mx0, 2));
        mx1 = fmaxf(mx1, __shfl_xor_sync(0xffffffffu, mx1, 1));
        mx1 = fmaxf(mx1, __shfl_xor_sync(0xffffffffu, mx1, 2));
        const float mn0 = fmaxf(m0, mx0), mn1 = fmaxf(m1, mx1);
        const float co0 = ex2f(m0 - mn0), co1 = ex2f(m1 - mn1);
        float sum0 = 0.0f, sum1 = 0.0f;
        #pragma unroll
        for (int j = 0; j < 8; j++) {
            const float p0 = ex2f(s[j][0] - mn0);
            const float p1 = ex2f(s[j][1] - mn0);
            const float p2 = ex2f(s[j][2] - mn1);
            const float p3 = ex2f(s[j][3] - mn1);
            sum0 += p0 + p1; sum1 += p2 + p3;
            const int c = j * 8 + 2 * tig;
            *(float2*)&Ps[swz(rr, c)]     = make_float2(f2tf(p0), f2tf(p1));
            *(float2*)&Ps[swz(rr + 8, c)] = make_float2(f2tf(p2), f2tf(p3));
        }
        sum0 += __shfl_xor_sync(0xffffffffu, sum0, 1);
        sum0 += __shfl_xor_sync(0xffffffffu, sum0, 2);
        sum1 += __shfl_xor_sync(0xffffffffu, sum1, 1);
        sum1 += __shfl_xor_sync(0xffffffffu, sum1, 2);
        l0 = l0 * co0 + sum0; m0 = mn0;
        l1 = l1 * co1 + sum1; m1 = mn1;

        #pragma unroll
        for (int j = 0; j < 8; j++) {
            o[j][0] *= co0; o[j][1] *= co0;
            o[j][2] *= co1; o[j][3] *= co1;
        }
        __syncwarp();

        #pragma unroll
        for (int kc = 0; kc < 8; kc++) {
            const int kk = kc * 8;
            unsigned af[4];
            {
                const int m  = lane >> 3;
                const int pr = wm * 16 + (m & 1) * 8 + l7;
                const int cc = kk + (m >> 1) * 4;
                ldsm4(af[0], af[1], af[2], af[3], &Ps[swz(pr, cc)]);
            }
            unsigned bf[8][2];
            #pragma unroll
            for (int jp = 0; jp < 4; jp++) {
                const int m  = lane >> 3;
                const int vr = (jp * 2 + (m >> 1)) * 8 + l7;
                const int cc = kk + (m & 1) * 4;
                ldsm4(bf[jp*2][0], bf[jp*2][1], bf[jp*2+1][0], bf[jp*2+1][1],
                      &Vt[swz(vr, cc)]);
            }
            #pragma unroll
            for (int j = 0; j < 8; j++)
                mma8(o[j], af, bf[j]);
        }
    }

    const float i0 = 1.0f / l0, i1 = 1.0f / l1;
    float* Og = g_att + ((size_t)(b * L_ + qB + wm * 16)) * D_ + h * HD_;
    #pragma unroll
    for (int j = 0; j < 8; j++) {
        const int c = j * 8 + 2 * tig;
        *(float2*)&Og[(size_t)gid * D_ + c] =
            make_float2(o[j][0] * i0, o[j][1] * i0);
        *(float2*)&Og[(size_t)(gid + 8) * D_ + c] =
            make_float2(o[j][2] * i1, o[j][3] * i1);
    }
}

// ---------------------------------------------------------------------------
// Launch.  Inputs: q, k, v, Wq, bq, Wk, bk, Wv, bv, Wo, bo
// ---------------------------------------------------------------------------
extern "C" void kernel_launch(void* const* d_in, const int* in_sizes, int n_in,
                              void* d_out, int out_size)
{
    (void)in_sizes; (void)n_in; (void)out_size;
    const float* q  = (const float*)d_in[0];
    const float* k  = (const float*)d_in[1];
    const float* v  = (const float*)d_in[2];
    const float* Wq = (const float*)d_in[3];
    const float* bq = (const float*)d_in[4];
    const float* Wk = (const float*)d_in[5];
    const float* bk = (const float*)d_in[6];
    const float* Wv = (const float*)d_in[7];
    const float* bv = (const float*)d_in[8];
    const float* Wo = (const float*)d_in[9];
    const float* bo = (const float*)d_in[10];
    float* out = (float*)d_out;

    cudaFuncSetAttribute(gemm_qkv, cudaFuncAttributeMaxDynamicSharedMemorySize,
                         GEMM_SMEM_BYTES);
    cudaFuncSetAttribute(gemm_o, cudaFuncAttributeMaxDynamicSharedMemorySize,
                         GEMM_SMEM_BYTES);
    cudaFuncSetAttribute(attn_tf32, cudaFuncAttributeMaxDynamicSharedMemorySize,
                         ATT_SMEM_BYTES);

    const dim3 qkvGrid(D_ / 256, M_ / 128, 3);   // (4, 64, 3)
    gemm_qkv<<<qkvGrid, 256, GEMM_SMEM_BYTES>>>(q, k, v, Wq, bq, Wk, bk, Wv, bv);

    const dim3 attGrid(L_ / 64, H_, B_);         // (32, 16, 4)
    attn_tf32<<<attGrid, 128, ATT_SMEM_BYTES>>>();

    const dim3 oGrid(D_ / 256, M_ / 128);        // (4, 64)
    gemm_o<<<oGrid, 256, GEMM_SMEM_BYTES>>>(Wo, bo, out);
}